// round 16
// baseline (speedup 1.0000x reference)
#include <cuda_runtime.h>
#include <cstdint>
#include <math.h>

#define N 4096
#define IN_F 256
#define HH 4
#define OF 128
#define HOF 512
#define SLOPE 0.2f

// Scratch (device globals: no allocations allowed)
__device__ float g_h[N * HOF];                 // 8 MB  [n][h*128+f] (fp32)
__device__ uint32_t g_hTb[HH * OF * (N / 2)];  // 4 MB  [h][f][pair, digit-swap perm'd]
__device__ float g_cih[HH * N];                // head-major ci
__device__ float g_cjh[HH * N];                // head-major cj

__device__ __forceinline__ uint32_t smem_u32(const void* p) {
    uint32_t a;
    asm("{ .reg .u64 t; cvta.to.shared.u64 t, %1; cvt.u32.u64 %0, t; }" : "=r"(a) : "l"(p));
    return a;
}
__device__ __forceinline__ float to_tf32(float x) {
    float r;
    asm("cvt.rna.tf32.f32 %0, %1;" : "=f"(r) : "f"(x));
    return r;
}
__device__ __forceinline__ uint32_t pack_bf16x2(float hi, float lo) {
    uint32_t d;
    asm("cvt.rn.bf16x2.f32 %0, %1, %2;" : "=r"(d) : "f"(hi), "f"(lo));
    return d;
}
#define CP_ASYNC16(dst_u32, src_ptr) \
    asm volatile("cp.async.cg.shared.global [%0], [%1], 16;" :: "r"(dst_u32), \
                 "l"(__cvta_generic_to_global(src_ptr)))
#define CP_COMMIT() asm volatile("cp.async.commit_group;" ::: "memory")
#define CP_WAIT0()  asm volatile("cp.async.wait_group 0;" ::: "memory")
#define CP_WAIT1()  asm volatile("cp.async.wait_group 1;" ::: "memory")

// tf32 m16n8k8 (kernel A only)
__device__ __forceinline__ void mma_tf32(float* c, const uint32_t* a, const uint32_t* b) {
    asm volatile(
        "mma.sync.aligned.m16n8k8.row.col.f32.tf32.tf32.f32 "
        "{%0,%1,%2,%3}, {%4,%5,%6,%7}, {%8,%9}, {%0,%1,%2,%3};"
        : "+f"(c[0]), "+f"(c[1]), "+f"(c[2]), "+f"(c[3])
        : "r"(a[0]), "r"(a[1]), "r"(a[2]), "r"(a[3]), "r"(b[0]), "r"(b[1]));
}
// bf16 m16n8k16 (kernel D)
__device__ __forceinline__ void mma_bf16(float* c, const uint32_t* a, const uint32_t* b) {
    asm volatile(
        "mma.sync.aligned.m16n8k16.row.col.f32.bf16.bf16.f32 "
        "{%0,%1,%2,%3}, {%4,%5,%6,%7}, {%8,%9}, {%0,%1,%2,%3};"
        : "+f"(c[0]), "+f"(c[1]), "+f"(c[2]), "+f"(c[3])
        : "r"(a[0]), "r"(a[1]), "r"(a[2]), "r"(a[3]), "r"(b[0]), "r"(b[1]));
}

// k-pair interleave for kernel A fragments (8-group)
__device__ __forceinline__ int kperm(int w) { return ((w & 3) << 1) | ((w >> 2) & 1); }
// digit-swap permutation of 16 (self-inverse): pair u -> column 4*(u&3)+(u>>2)
__device__ __forceinline__ int cperm16(int u) { return ((u & 3) << 2) | (u >> 2); }

// ---------------------------------------------------------------------------
// Kernel A (tf32 mma, cp.async 2-stage): g_h = x @ W ; g_hTb = bf16x2 transpose
// with per-16-pair digit-swap permutation for kernel D's LDS.128 feeds.
// ---------------------------------------------------------------------------
#define XS_STRIDE 40
#define WS_STRIDE 72
#define XS_STAGE (64 * XS_STRIDE)
#define WS_STAGE (32 * WS_STRIDE)
#define TSW 65
__global__ __launch_bounds__(256) void k_gemm_h(const float* __restrict__ X,
                                                const float* __restrict__ W) {
    __shared__ float SM[2 * XS_STAGE + 2 * WS_STAGE];
    const uint32_t sb = smem_u32(SM);
    const int tid = threadIdx.x;
    const int wid = tid >> 5;
    const int lane = tid & 31;
    const int g = lane >> 2;
    const int t = lane & 3;
    const int row0 = blockIdx.y * 64;
    const int col0 = blockIdx.x * 64;
    const int mrow0 = (wid & 1) * 32;
    const int ncol0 = (wid >> 1) * 16;

    const int xm = tid >> 3, xq = tid & 7;
    const int wk = tid >> 4, wn4 = tid & 15;

    {
        const uint32_t xd = sb;
        const uint32_t wd = sb + 2 * XS_STAGE * 4;
#pragma unroll
        for (int it = 0; it < 2; it++) {
            int m = xm + 32 * it;
            CP_ASYNC16(xd + (uint32_t)(m * XS_STRIDE + xq * 4) * 4,
                       X + (size_t)(row0 + m) * IN_F + xq * 4);
            int k = wk + 16 * it;
            CP_ASYNC16(wd + (uint32_t)(k * WS_STRIDE + wn4 * 4) * 4,
                       W + (size_t)k * HOF + col0 + wn4 * 4);
        }
        CP_COMMIT();
    }

    float acc[2][2][4];
#pragma unroll
    for (int a = 0; a < 2; a++)
#pragma unroll
        for (int b = 0; b < 2; b++)
#pragma unroll
            for (int c = 0; c < 4; c++) acc[a][b][c] = 0.0f;

    for (int kk = 0; kk < 8; kk++) {
        const int s = kk & 1;
        if (kk + 1 < 8) {
            const int k0 = (kk + 1) * 32;
            const uint32_t xd = sb + (uint32_t)(((kk + 1) & 1) * XS_STAGE) * 4;
            const uint32_t wd = sb + (uint32_t)(2 * XS_STAGE + ((kk + 1) & 1) * WS_STAGE) * 4;
#pragma unroll
            for (int it = 0; it < 2; it++) {
                int m = xm + 32 * it;
                CP_ASYNC16(xd + (uint32_t)(m * XS_STRIDE + xq * 4) * 4,
                           X + (size_t)(row0 + m) * IN_F + k0 + xq * 4);
                int k = wk + 16 * it;
                CP_ASYNC16(wd + (uint32_t)(k * WS_STRIDE + wn4 * 4) * 4,
                           W + (size_t)(k0 + k) * HOF + col0 + wn4 * 4);
            }
        }
        CP_COMMIT();
        CP_WAIT1();
        __syncthreads();

        const float* XS = SM + s * XS_STAGE;
        const float* WS = SM + 2 * XS_STAGE + s * WS_STAGE;
#pragma unroll
        for (int ks = 0; ks < 4; ks++) {
            const int kb = ks * 8;
            uint32_t bfr[2][2];
#pragma unroll
            for (int nt = 0; nt < 2; nt++) {
                int n = ncol0 + nt * 8 + g;
                bfr[nt][0] = __float_as_uint(to_tf32(WS[(kb + t) * WS_STRIDE + n]));
                bfr[nt][1] = __float_as_uint(to_tf32(WS[(kb + t + 4) * WS_STRIDE + n]));
            }
#pragma unroll
            for (int mt = 0; mt < 2; mt++) {
                int r0 = mrow0 + mt * 16;
                uint32_t afr[4];
                afr[0] = __float_as_uint(to_tf32(XS[(r0 + g) * XS_STRIDE + kb + t]));
                afr[1] = __float_as_uint(to_tf32(XS[(r0 + g + 8) * XS_STRIDE + kb + t]));
                afr[2] = __float_as_uint(to_tf32(XS[(r0 + g) * XS_STRIDE + kb + t + 4]));
                afr[3] = __float_as_uint(to_tf32(XS[(r0 + g + 8) * XS_STRIDE + kb + t + 4]));
#pragma unroll
                for (int nt = 0; nt < 2; nt++) mma_tf32(acc[mt][nt], afr, bfr[nt]);
            }
        }
        __syncthreads();
    }

    float* TS = SM;
#pragma unroll
    for (int mt = 0; mt < 2; mt++) {
        const int ja = mrow0 + mt * 16 + g;
        const int jb = ja + 8;
#pragma unroll
        for (int nt = 0; nt < 2; nt++) {
            const int cl = ncol0 + nt * 8 + 2 * t;
            TS[cl * TSW + ja] = acc[mt][nt][0];
            TS[(cl + 1) * TSW + ja] = acc[mt][nt][1];
            TS[cl * TSW + jb] = acc[mt][nt][2];
            TS[(cl + 1) * TSW + jb] = acc[mt][nt][3];
        }
    }
    __syncthreads();

#pragma unroll
    for (int r = 0; r < 8; r++) {
        const int j = wid * 8 + r;
#pragma unroll
        for (int it = 0; it < 2; it++) {
            const int cl = it * 32 + lane;
            g_h[(size_t)(row0 + j) * HOF + col0 + cl] = TS[cl * TSW + j];
        }
    }
    // g_hTb: bf16x2 pairs, digit-swap perm within each 16-pair group
    {
        const int hd = col0 >> 7;
        const int f0 = col0 & 127;
        const int p = lane;                              // pair 0..31 in block
        const int pos = (p & ~15) | cperm16(p & 15);
#pragma unroll
        for (int r = 0; r < 8; r++) {
            const int cl = wid * 8 + r;
            uint32_t* dst = g_hTb + ((size_t)hd * OF + f0 + cl) * (N / 2) + row0 / 2;
            float lo = TS[cl * TSW + 2 * p];
            float hi = TS[cl * TSW + 2 * p + 1];
            dst[pos] = pack_bf16x2(hi, lo);
        }
    }
}

// ---------------------------------------------------------------------------
// Kernel B: ci / cj coefficients (head-major outputs). One warp per (n,h).
// ---------------------------------------------------------------------------
__global__ __launch_bounds__(128) void k_coeff(const float* __restrict__ a_i,
                                               const float* __restrict__ a_j) {
    const int n = blockIdx.x;
    const int h = threadIdx.x >> 5;
    const int lane = threadIdx.x & 31;

    float4 hv = *(const float4*)&g_h[n * HOF + h * OF + lane * 4];
    float4 ai = *(const float4*)&a_i[h * OF + lane * 4];
    float4 aj = *(const float4*)&a_j[h * OF + lane * 4];
    float si = hv.x * ai.x + hv.y * ai.y + hv.z * ai.z + hv.w * ai.w;
    float sj = hv.x * aj.x + hv.y * aj.y + hv.z * aj.z + hv.w * aj.w;
#pragma unroll
    for (int o = 16; o > 0; o >>= 1) {
        si += __shfl_down_sync(0xffffffffu, si, o);
        sj += __shfl_down_sync(0xffffffffu, sj, o);
    }
    if (lane == 0) {
        g_cih[h * N + n] = si;
        g_cjh[h * N + n] = sj;
    }
}

// ---------------------------------------------------------------------------
// Kernel D (bf16 m16n8k16, BM=32, 2 chunks/barrier, LDS.128 feeds):
// 4-stage P + H rings. Iter k: P(2k),P(2k+1) -> wait -> bar ->
//   issue H(2k+2),H(2k+3) -> mma(2k),mma(2k+1).
// LDW=16 u32 (no pad): LDS.128 phases cover all 32 banks (stride 16 mod 32).
// ---------------------------------------------------------------------------
#define D_BM 32
#define D_BK 32
#define NCHUNK (N / D_BK)
#define NITER (NCHUNK / 2)
#define LDW 16
#define HSTG 2048                        // u32 per H stage (128 x 16)
#define PSTG 512                         // u32 per P stage (32 x 16)

#define OFF_CI   0
#define OFF_BIAS 64
#define OFF_Z    192
#define OFF_H    256                     // 4 stages x 2048
#define OFF_P    (OFF_H + 4*HSTG)        // 4 stages x 512
#define SM_WORDS (OFF_P + 4*PSTG)
#define SM_BYTES (SM_WORDS * 4)

__global__ __launch_bounds__(256, 4) void k_out_tc(const float* __restrict__ adj,
                                                   const float* __restrict__ bias,
                                                   float* __restrict__ out) {
    extern __shared__ float smf[];
    uint32_t* smu = (uint32_t*)smf;
    const uint32_t sb = smem_u32(smf);
    const int tid = threadIdx.x;
    const int wid = tid >> 5;
    const int lane = tid & 31;
    const int g = lane >> 2;
    const int t = lane & 3;
    const int i0 = blockIdx.x * D_BM;
    const int head = blockIdx.y;
    const int n0w = wid * 16;

    if (tid < 32) smf[OFF_CI + tid] = g_cih[head * N + i0 + tid];
    if (tid >= 64 && tid < 192) smf[OFF_BIAS + tid - 64] = bias[head * OF + tid - 64];

    // prologue: H(0)->stage0, H(1)->stage1 in ONE commit group
    {
#pragma unroll
        for (int c = 0; c < 2; c++) {
            const uint32_t h_dst = sb + (uint32_t)(OFF_H + c * HSTG) * 4;
#pragma unroll
            for (int it = 0; it < 2; it++) {
                int idx = tid + 256 * it;
                int f = idx >> 2, q = idx & 3;
                CP_ASYNC16(h_dst + (uint32_t)(f * LDW + q * 4) * 4,
                           g_hTb + ((size_t)head * OF + f) * (N / 2) + c * 16 + q * 4);
            }
        }
        CP_COMMIT();
    }

    // P-producer: 16 threads/row group; 2 row-iterations cover 32 rows
    const int prow = tid >> 4;            // 0..15
    const int jp = tid & 15;              // pair within chunk
    const int pcol = cperm16(jp);

    // adj + cj for chunks 0,1
    float2 aval[2][2], anx[2][2];
    float2 cjv[2], cjn[2];
#pragma unroll
    for (int c = 0; c < 2; c++) {
#pragma unroll
        for (int it = 0; it < 2; it++)
            aval[c][it] = *(const float2*)&adj[(size_t)(i0 + prow + 16 * it) * N +
                                               c * D_BK + 2 * jp];
        cjv[c] = *(const float2*)&g_cjh[head * N + c * D_BK + 2 * jp];
    }

    __syncthreads();

    float acc[2][2][4];
#pragma unroll
    for (int a = 0; a < 2; a++)
#pragma unroll
        for (int b = 0; b < 2; b++)
#pragma unroll
            for (int c = 0; c < 4; c++) acc[a][b][c] = 0.0f;
    float zacc[2] = {0.0f, 0.0f};

    const float* ci_s = smf + OFF_CI;

    for (int k = 0; k < NITER; k++) {
        const int c0 = 2 * k;

        // prefetch adj/cj for chunks c0+2, c0+3
        if (k + 1 < NITER) {
#pragma unroll
            for (int c = 0; c < 2; c++) {
                const int jc = (c0 + 2 + c) * D_BK;
#pragma unroll
                for (int it = 0; it < 2; it++)
                    anx[c][it] = *(const float2*)&adj[(size_t)(i0 + prow + 16 * it) * N +
                                                      jc + 2 * jp];
                cjn[c] = *(const float2*)&g_cjh[head * N + jc + 2 * jp];
            }
        }

        // P(c0), P(c0+1) into stages (c0)&3, (c0+1)&3
#pragma unroll
        for (int c = 0; c < 2; c++) {
            uint32_t* PS = smu + OFF_P + ((c0 + c) & 3) * PSTG;
#pragma unroll
            for (int it = 0; it < 2; it++) {
                const int r = prow + 16 * it;
                const float civ = ci_s[r];
                float s0 = civ + cjv[c].x;
                float s1 = civ + cjv[c].y;
                s0 = fmaxf(s0, SLOPE * s0) * aval[c][it].x;
                s1 = fmaxf(s1, SLOPE * s1) * aval[c][it].y;
                float e0 = __expf(s0);
                float e1 = __expf(s1);
                zacc[it] += e0 + e1;
                PS[r * LDW + pcol] = pack_bf16x2(e1 * aval[c][it].y, e0 * aval[c][it].x);
            }
        }
#pragma unroll
        for (int c = 0; c < 2; c++) {
            aval[c][0] = anx[c][0];
            aval[c][1] = anx[c][1];
            cjv[c] = cjn[c];
        }

        CP_WAIT0();       // H(c0), H(c0+1) complete
        __syncthreads();  // P visible; mma(iter k-1) done everywhere

        // issue H(c0+2), H(c0+3) (their stages' readers were mma(iter k-1))
        if (k + 1 < NITER) {
#pragma unroll
            for (int c = 0; c < 2; c++) {
                const int cc = c0 + 2 + c;
                const uint32_t h_dst = sb + (uint32_t)(OFF_H + (cc & 3) * HSTG) * 4;
                const int jp1 = cc * 16;
#pragma unroll
                for (int it = 0; it < 2; it++) {
                    int idx = tid + 256 * it;
                    int f = idx >> 2, q = idx & 3;
                    CP_ASYNC16(h_dst + (uint32_t)(f * LDW + q * 4) * 4,
                               g_hTb + ((size_t)head * OF + f) * (N / 2) + jp1 + q * 4);
                }
            }
            CP_COMMIT();
        }

        // mma(c0), mma(c0+1): LDS.128 fragment feeds
#pragma unroll
        for (int c = 0; c < 2; c++) {
            const uint32_t* HS = smu + OFF_H + ((c0 + c) & 3) * HSTG;
            const uint32_t* PSb = smu + OFF_P + ((c0 + c) & 3) * PSTG;
            uint4 vb0 = *(const uint4*)&HS[(n0w + g) * LDW + 4 * t];
            uint4 vb1 = *(const uint4*)&HS[(n0w + 8 + g) * LDW + 4 * t];
            uint4 va0 = *(const uint4*)&PSb[g * LDW + 4 * t];
            uint4 va1 = *(const uint4*)&PSb[(g + 8) * LDW + 4 * t];
            uint4 va2 = *(const uint4*)&PSb[(16 + g) * LDW + 4 * t];
            uint4 va3 = *(const uint4*)&PSb[(24 + g) * LDW + 4 * t];
            // ks0: pairs (t, t+4)
            {
                uint32_t a0[4] = {va0.x, va1.x, va0.y, va1.y};
                uint32_t a1[4] = {va2.x, va3.x, va2.y, va3.y};
                uint32_t b0[2] = {vb0.x, vb0.y};
                uint32_t b1[2] = {vb1.x, vb1.y};
                mma_bf16(acc[0][0], a0, b0);
                mma_bf16(acc[0][1], a0, b1);
                mma_bf16(acc[1][0], a1, b0);
                mma_bf16(acc[1][1], a1, b1);
            }
            // ks1: pairs (8+t, 12+t)
            {
                uint32_t a0[4] = {va0.z, va1.z, va0.w, va1.w};
                uint32_t a1[4] = {va2.z, va3.z, va2.w, va3.w};
                uint32_t b0[2] = {vb0.z, vb0.w};
                uint32_t b1[2] = {vb1.z, vb1.w};
                mma_bf16(acc[0][0], a0, b0);
                mma_bf16(acc[0][1], a0, b1);
                mma_bf16(acc[1][0], a1, b0);
                mma_bf16(acc[1][1], a1, b1);
            }
        }
    }

    // z reduce: 16 lanes (jp) share a row; xor-reduce within 16-lane halves
#pragma unroll
    for (int it = 0; it < 2; it++) {
        float v = zacc[it];
#pragma unroll
        for (int o = 8; o > 0; o >>= 1) v += __shfl_xor_sync(0xffffffffu, v, o);
        if ((lane & 15) == 0) smf[OFF_Z + prow + 16 * it] = v;
    }
    __syncthreads();

    // epilogue: scale by 1/z, add bias
    const float* biasS = smf + OFF_BIAS;
    const float* zS = smf + OFF_Z;
#pragma unroll
    for (int mt = 0; mt < 2; mt++) {
        const int r = mt * 16 + g;
        const int ra = i0 + r;
        const float za = 1.0f / zS[r];
        const float zb = 1.0f / zS[r + 8];
#pragma unroll
        for (int nt = 0; nt < 2; nt++) {
            const int col = n0w + nt * 8 + 2 * t;
            float2 v0, v1;
            v0.x = acc[mt][nt][0] * za + biasS[col];
            v0.y = acc[mt][nt][1] * za + biasS[col + 1];
            v1.x = acc[mt][nt][2] * zb + biasS[col];
            v1.y = acc[mt][nt][3] * zb + biasS[col + 1];
            *(float2*)&out[(size_t)ra * HOF + head * OF + col] = v0;
            *(float2*)&out[(size_t)(ra + 8) * HOF + head * OF + col] = v1;
        }
    }
}

// ---------------------------------------------------------------------------
extern "C" void kernel_launch(void* const* d_in, const int* in_sizes, int n_in,
                              void* d_out, int out_size) {
    const float* x    = (const float*)d_in[0];   // (4096, 256)
    const float* adj  = (const float*)d_in[1];   // (4096, 4096)
    const float* W    = (const float*)d_in[2];   // (256, 512)
    const float* a_i  = (const float*)d_in[3];   // (4, 128, 1)
    const float* a_j  = (const float*)d_in[4];   // (4, 128, 1)
    const float* bias = (const float*)d_in[5];   // (512,)
    float* out = (float*)d_out;                  // (4096, 512)

    cudaFuncSetAttribute(k_out_tc, cudaFuncAttributeMaxDynamicSharedMemorySize, SM_BYTES);

    dim3 gA(HOF / 64, N / 64);
    k_gemm_h<<<gA, 256>>>(x, W);
    k_coeff<<<N, 128>>>(a_i, a_j);
    dim3 gD(N / D_BM, HH);
    k_out_tc<<<gD, 256, SM_BYTES>>>(adj, bias, out);
}

// round 17
// speedup vs baseline: 1.1513x; 1.1513x over previous
#include <cuda_runtime.h>
#include <cstdint>
#include <math.h>

#define N 4096
#define IN_F 256
#define HH 4
#define OF 128
#define HOF 512
#define SLOPE 0.2f
#define LOG2E 1.4426950408889634f

// Scratch (device globals: no allocations allowed)
__device__ float g_h[N * HOF];                 // 8 MB  [n][h*128+f] (fp32)
__device__ uint32_t g_hTb[HH * OF * (N / 2)];  // 4 MB  [h][f][pair, digit-swap perm'd]
__device__ float g_cih[HH * N];                // head-major ci (pre-scaled by log2e)
__device__ float g_cjh[HH * N];                // head-major cj (pre-scaled by log2e)

__device__ __forceinline__ uint32_t smem_u32(const void* p) {
    uint32_t a;
    asm("{ .reg .u64 t; cvta.to.shared.u64 t, %1; cvt.u32.u64 %0, t; }" : "=r"(a) : "l"(p));
    return a;
}
__device__ __forceinline__ float to_tf32(float x) {
    float r;
    asm("cvt.rna.tf32.f32 %0, %1;" : "=f"(r) : "f"(x));
    return r;
}
__device__ __forceinline__ float ex2f(float x) {
    float r;
    asm("ex2.approx.ftz.f32 %0, %1;" : "=f"(r) : "f"(x));
    return r;
}
__device__ __forceinline__ uint32_t pack_bf16x2(float hi, float lo) {
    uint32_t d;
    asm("cvt.rn.bf16x2.f32 %0, %1, %2;" : "=r"(d) : "f"(hi), "f"(lo));
    return d;
}
#define CP_ASYNC16(dst_u32, src_ptr) \
    asm volatile("cp.async.cg.shared.global [%0], [%1], 16;" :: "r"(dst_u32), \
                 "l"(__cvta_generic_to_global(src_ptr)))
#define CP_COMMIT() asm volatile("cp.async.commit_group;" ::: "memory")
#define CP_WAIT1()  asm volatile("cp.async.wait_group 1;" ::: "memory")

// tf32 m16n8k8 (kernel A only)
__device__ __forceinline__ void mma_tf32(float* c, const uint32_t* a, const uint32_t* b) {
    asm volatile(
        "mma.sync.aligned.m16n8k8.row.col.f32.tf32.tf32.f32 "
        "{%0,%1,%2,%3}, {%4,%5,%6,%7}, {%8,%9}, {%0,%1,%2,%3};"
        : "+f"(c[0]), "+f"(c[1]), "+f"(c[2]), "+f"(c[3])
        : "r"(a[0]), "r"(a[1]), "r"(a[2]), "r"(a[3]), "r"(b[0]), "r"(b[1]));
}
// bf16 m16n8k16 (kernel D)
__device__ __forceinline__ void mma_bf16(float* c, const uint32_t* a, const uint32_t* b) {
    asm volatile(
        "mma.sync.aligned.m16n8k16.row.col.f32.bf16.bf16.f32 "
        "{%0,%1,%2,%3}, {%4,%5,%6,%7}, {%8,%9}, {%0,%1,%2,%3};"
        : "+f"(c[0]), "+f"(c[1]), "+f"(c[2]), "+f"(c[3])
        : "r"(a[0]), "r"(a[1]), "r"(a[2]), "r"(a[3]), "r"(b[0]), "r"(b[1]));
}

// digit-swap permutation of 16 (self-inverse): pair u -> column 4*(u&3)+(u>>2)
__device__ __forceinline__ int cperm16(int u) { return ((u & 3) << 2) | (u >> 2); }

// ---------------------------------------------------------------------------
// Kernel A (tf32 mma, cp.async 2-stage): g_h = x @ W ; g_hTb = bf16x2 transpose
// (unchanged core — measured 20.4 us)
// ---------------------------------------------------------------------------
#define XS_STRIDE 40
#define WS_STRIDE 72
#define XS_STAGE (64 * XS_STRIDE)
#define WS_STAGE (32 * WS_STRIDE)
#define TSW 65
__global__ __launch_bounds__(256) void k_gemm_h(const float* __restrict__ X,
                                                const float* __restrict__ W) {
    __shared__ float SM[2 * XS_STAGE + 2 * WS_STAGE];
    const uint32_t sb = smem_u32(SM);
    const int tid = threadIdx.x;
    const int wid = tid >> 5;
    const int lane = tid & 31;
    const int g = lane >> 2;
    const int t = lane & 3;
    const int row0 = blockIdx.y * 64;
    const int col0 = blockIdx.x * 64;
    const int mrow0 = (wid & 1) * 32;
    const int ncol0 = (wid >> 1) * 16;

    const int xm = tid >> 3, xq = tid & 7;
    const int wk = tid >> 4, wn4 = tid & 15;

    {
        const uint32_t xd = sb;
        const uint32_t wd = sb + 2 * XS_STAGE * 4;
#pragma unroll
        for (int it = 0; it < 2; it++) {
            int m = xm + 32 * it;
            CP_ASYNC16(xd + (uint32_t)(m * XS_STRIDE + xq * 4) * 4,
                       X + (size_t)(row0 + m) * IN_F + xq * 4);
            int k = wk + 16 * it;
            CP_ASYNC16(wd + (uint32_t)(k * WS_STRIDE + wn4 * 4) * 4,
                       W + (size_t)k * HOF + col0 + wn4 * 4);
        }
        CP_COMMIT();
    }

    float acc[2][2][4];
#pragma unroll
    for (int a = 0; a < 2; a++)
#pragma unroll
        for (int b = 0; b < 2; b++)
#pragma unroll
            for (int c = 0; c < 4; c++) acc[a][b][c] = 0.0f;

    for (int kk = 0; kk < 8; kk++) {
        const int s = kk & 1;
        if (kk + 1 < 8) {
            const int k0 = (kk + 1) * 32;
            const uint32_t xd = sb + (uint32_t)(((kk + 1) & 1) * XS_STAGE) * 4;
            const uint32_t wd = sb + (uint32_t)(2 * XS_STAGE + ((kk + 1) & 1) * WS_STAGE) * 4;
#pragma unroll
            for (int it = 0; it < 2; it++) {
                int m = xm + 32 * it;
                CP_ASYNC16(xd + (uint32_t)(m * XS_STRIDE + xq * 4) * 4,
                           X + (size_t)(row0 + m) * IN_F + k0 + xq * 4);
                int k = wk + 16 * it;
                CP_ASYNC16(wd + (uint32_t)(k * WS_STRIDE + wn4 * 4) * 4,
                           W + (size_t)(k0 + k) * HOF + col0 + wn4 * 4);
            }
        }
        CP_COMMIT();
        CP_WAIT1();
        __syncthreads();

        const float* XS = SM + s * XS_STAGE;
        const float* WS = SM + 2 * XS_STAGE + s * WS_STAGE;
#pragma unroll
        for (int ks = 0; ks < 4; ks++) {
            const int kb = ks * 8;
            uint32_t bfr[2][2];
#pragma unroll
            for (int nt = 0; nt < 2; nt++) {
                int n = ncol0 + nt * 8 + g;
                bfr[nt][0] = __float_as_uint(to_tf32(WS[(kb + t) * WS_STRIDE + n]));
                bfr[nt][1] = __float_as_uint(to_tf32(WS[(kb + t + 4) * WS_STRIDE + n]));
            }
#pragma unroll
            for (int mt = 0; mt < 2; mt++) {
                int r0 = mrow0 + mt * 16;
                uint32_t afr[4];
                afr[0] = __float_as_uint(to_tf32(XS[(r0 + g) * XS_STRIDE + kb + t]));
                afr[1] = __float_as_uint(to_tf32(XS[(r0 + g + 8) * XS_STRIDE + kb + t]));
                afr[2] = __float_as_uint(to_tf32(XS[(r0 + g) * XS_STRIDE + kb + t + 4]));
                afr[3] = __float_as_uint(to_tf32(XS[(r0 + g + 8) * XS_STRIDE + kb + t + 4]));
#pragma unroll
                for (int nt = 0; nt < 2; nt++) mma_tf32(acc[mt][nt], afr, bfr[nt]);
            }
        }
        __syncthreads();
    }

    float* TS = SM;
#pragma unroll
    for (int mt = 0; mt < 2; mt++) {
        const int ja = mrow0 + mt * 16 + g;
        const int jb = ja + 8;
#pragma unroll
        for (int nt = 0; nt < 2; nt++) {
            const int cl = ncol0 + nt * 8 + 2 * t;
            TS[cl * TSW + ja] = acc[mt][nt][0];
            TS[(cl + 1) * TSW + ja] = acc[mt][nt][1];
            TS[cl * TSW + jb] = acc[mt][nt][2];
            TS[(cl + 1) * TSW + jb] = acc[mt][nt][3];
        }
    }
    __syncthreads();

#pragma unroll
    for (int r = 0; r < 8; r++) {
        const int j = wid * 8 + r;
#pragma unroll
        for (int it = 0; it < 2; it++) {
            const int cl = it * 32 + lane;
            g_h[(size_t)(row0 + j) * HOF + col0 + cl] = TS[cl * TSW + j];
        }
    }
    // g_hTb: bf16x2 pairs, digit-swap perm within each 16-pair group
    {
        const int hd = col0 >> 7;
        const int f0 = col0 & 127;
        const int p = lane;                              // pair 0..31 in block
        const int pos = (p & ~15) | cperm16(p & 15);
#pragma unroll
        for (int r = 0; r < 8; r++) {
            const int cl = wid * 8 + r;
            uint32_t* dst = g_hTb + ((size_t)hd * OF + f0 + cl) * (N / 2) + row0 / 2;
            float lo = TS[cl * TSW + 2 * p];
            float hi = TS[cl * TSW + 2 * p + 1];
            dst[pos] = pack_bf16x2(hi, lo);
        }
    }
}

// ---------------------------------------------------------------------------
// Kernel B: ci / cj coefficients (head-major, PRE-SCALED by log2e so kernel D
// can use ex2 directly: exp(lrelu(ci+cj)*a) == ex2(lrelu(ci'+cj')*a) since
// lrelu is positively homogeneous). One warp per (n,h).
// ---------------------------------------------------------------------------
__global__ __launch_bounds__(128) void k_coeff(const float* __restrict__ a_i,
                                               const float* __restrict__ a_j) {
    const int n = blockIdx.x;
    const int h = threadIdx.x >> 5;
    const int lane = threadIdx.x & 31;

    float4 hv = *(const float4*)&g_h[n * HOF + h * OF + lane * 4];
    float4 ai = *(const float4*)&a_i[h * OF + lane * 4];
    float4 aj = *(const float4*)&a_j[h * OF + lane * 4];
    float si = hv.x * ai.x + hv.y * ai.y + hv.z * ai.z + hv.w * ai.w;
    float sj = hv.x * aj.x + hv.y * aj.y + hv.z * aj.z + hv.w * aj.w;
#pragma unroll
    for (int o = 16; o > 0; o >>= 1) {
        si += __shfl_down_sync(0xffffffffu, si, o);
        sj += __shfl_down_sync(0xffffffffu, sj, o);
    }
    if (lane == 0) {
        g_cih[h * N + n] = si * LOG2E;
        g_cjh[h * N + n] = sj * LOG2E;
    }
}

// ---------------------------------------------------------------------------
// Kernel D (bf16 m16n8k16, BM=32, H via direct LDG.128 from L2/L1):
// SMEM holds ONLY P (2 regions x 2 chunks x 32x16 u32). Per iter (2 chunks):
//   load adj/cj -> P into region k&1 -> ONE __syncthreads -> mma with
//   B-fragments LDG.128'd straight from g_hTb (L1-absorbed 8-warp reuse).
// Region reuse guarded by next iter's barrier + program order.
// ---------------------------------------------------------------------------
#define D_BM 32
#define D_BK 32
#define NCHUNK (N / D_BK)
#define NITER (NCHUNK / 2)
#define LDW 16
#define PREG 1024                        // u32 per region (2 chunks x 32x16)

#define OFF_CI   0
#define OFF_BIAS 64
#define OFF_Z    192
#define OFF_P    256                     // 2 regions x 1024
#define SM_WORDS (OFF_P + 2*PREG)
#define SM_BYTES (SM_WORDS * 4)

__global__ __launch_bounds__(256, 4) void k_out_tc(const float* __restrict__ adj,
                                                   const float* __restrict__ bias,
                                                   float* __restrict__ out) {
    extern __shared__ float smf[];
    uint32_t* smu = (uint32_t*)smf;
    const int tid = threadIdx.x;
    const int wid = tid >> 5;
    const int lane = tid & 31;
    const int g = lane >> 2;
    const int t = lane & 3;
    const int i0 = blockIdx.x * D_BM;
    const int head = blockIdx.y;
    const int n0w = wid * 16;

    if (tid < 32) smf[OFF_CI + tid] = g_cih[head * N + i0 + tid];
    if (tid >= 64 && tid < 192) smf[OFF_BIAS + tid - 64] = bias[head * OF + tid - 64];

    // P-producer mapping: 16 threads per row-group; 2 row-iterations x 2 chunks
    const int prow = tid >> 4;            // 0..15
    const int jp = tid & 15;              // pair within chunk
    const int pcol = cperm16(jp);

    __syncthreads();

    float acc[2][2][4];
#pragma unroll
    for (int a = 0; a < 2; a++)
#pragma unroll
        for (int b = 0; b < 2; b++)
#pragma unroll
            for (int c = 0; c < 4; c++) acc[a][b][c] = 0.0f;
    float zacc[2] = {0.0f, 0.0f};

    const float* ci_s = smf + OFF_CI;
    // B row base pointers (per-thread constant)
    const uint32_t* hrow0 = g_hTb + ((size_t)head * OF + n0w + g) * (N / 2) + 4 * t;
    const uint32_t* hrow1 = g_hTb + ((size_t)head * OF + n0w + 8 + g) * (N / 2) + 4 * t;

    for (int k = 0; k < NITER; k++) {
        const int c0 = 2 * k;
        uint32_t* PR = smu + OFF_P + (k & 1) * PREG;

        // ---- load adj + cj for both chunks, compute P into region k&1 ----
#pragma unroll
        for (int c = 0; c < 2; c++) {
            const int jb = (c0 + c) * D_BK + 2 * jp;
            const float2 cj2 = *(const float2*)&g_cjh[head * N + jb];
#pragma unroll
            for (int it = 0; it < 2; it++) {
                const int r = prow + 16 * it;
                const float2 av = *(const float2*)&adj[(size_t)(i0 + r) * N + jb];
                const float civ = ci_s[r];
                float s0 = civ + cj2.x;
                float s1 = civ + cj2.y;
                s0 = fmaxf(s0, SLOPE * s0) * av.x;
                s1 = fmaxf(s1, SLOPE * s1) * av.y;
                float e0 = ex2f(s0);
                float e1 = ex2f(s1);
                zacc[it] += e0 + e1;
                PR[c * 512 + r * LDW + pcol] = pack_bf16x2(e1 * av.y, e0 * av.x);
            }
        }

        __syncthreads();   // P(region k&1) visible; region (k&1) reads of
                           // iter k-2 finished before bar(k-1) in program order

        // ---- mma both chunks: B via LDG.128 (L1), A via LDS.128 ----
#pragma unroll
        for (int c = 0; c < 2; c++) {
            const int jpair = (c0 + c) * 16;
            uint4 vb0 = *(const uint4*)(hrow0 + jpair);
            uint4 vb1 = *(const uint4*)(hrow1 + jpair);
            const uint32_t* PSb = PR + c * 512;
            uint4 va0 = *(const uint4*)&PSb[g * LDW + 4 * t];
            uint4 va1 = *(const uint4*)&PSb[(g + 8) * LDW + 4 * t];
            uint4 va2 = *(const uint4*)&PSb[(16 + g) * LDW + 4 * t];
            uint4 va3 = *(const uint4*)&PSb[(24 + g) * LDW + 4 * t];
            {
                uint32_t a0[4] = {va0.x, va1.x, va0.y, va1.y};
                uint32_t a1[4] = {va2.x, va3.x, va2.y, va3.y};
                uint32_t b0[2] = {vb0.x, vb0.y};
                uint32_t b1[2] = {vb1.x, vb1.y};
                mma_bf16(acc[0][0], a0, b0);
                mma_bf16(acc[0][1], a0, b1);
                mma_bf16(acc[1][0], a1, b0);
                mma_bf16(acc[1][1], a1, b1);
            }
            {
                uint32_t a0[4] = {va0.z, va1.z, va0.w, va1.w};
                uint32_t a1[4] = {va2.z, va3.z, va2.w, va3.w};
                uint32_t b0[2] = {vb0.z, vb0.w};
                uint32_t b1[2] = {vb1.z, vb1.w};
                mma_bf16(acc[0][0], a0, b0);
                mma_bf16(acc[0][1], a0, b1);
                mma_bf16(acc[1][0], a1, b0);
                mma_bf16(acc[1][1], a1, b1);
            }
        }
    }

    // z reduce: 16 lanes (jp) share a row; xor-reduce within 16-lane halves
#pragma unroll
    for (int it = 0; it < 2; it++) {
        float v = zacc[it];
#pragma unroll
        for (int o = 8; o > 0; o >>= 1) v += __shfl_xor_sync(0xffffffffu, v, o);
        if ((lane & 15) == 0) smf[OFF_Z + prow + 16 * it] = v;
    }
    __syncthreads();

    // epilogue: scale by 1/z, add bias
    const float* biasS = smf + OFF_BIAS;
    const float* zS = smf + OFF_Z;
#pragma unroll
    for (int mt = 0; mt < 2; mt++) {
        const int r = mt * 16 + g;
        const int ra = i0 + r;
        const float za = 1.0f / zS[r];
        const float zb = 1.0f / zS[r + 8];
#pragma unroll
        for (int nt = 0; nt < 2; nt++) {
            const int col = n0w + nt * 8 + 2 * t;
            float2 v0, v1;
            v0.x = acc[mt][nt][0] * za + biasS[col];
            v0.y = acc[mt][nt][1] * za + biasS[col + 1];
            v1.x = acc[mt][nt][2] * zb + biasS[col];
            v1.y = acc[mt][nt][3] * zb + biasS[col + 1];
            *(float2*)&out[(size_t)ra * HOF + head * OF + col] = v0;
            *(float2*)&out[(size_t)(ra + 8) * HOF + head * OF + col] = v1;
        }
    }
}

// ---------------------------------------------------------------------------
extern "C" void kernel_launch(void* const* d_in, const int* in_sizes, int n_in,
                              void* d_out, int out_size) {
    const float* x    = (const float*)d_in[0];   // (4096, 256)
    const float* adj  = (const float*)d_in[1];   // (4096, 4096)
    const float* W    = (const float*)d_in[2];   // (256, 512)
    const float* a_i  = (const float*)d_in[3];   // (4, 128, 1)
    const float* a_j  = (const float*)d_in[4];   // (4, 128, 1)
    const float* bias = (const float*)d_in[5];   // (512,)
    float* out = (float*)d_out;                  // (4096, 512)

    cudaFuncSetAttribute(k_out_tc, cudaFuncAttributeMaxDynamicSharedMemorySize, SM_BYTES);

    dim3 gA(HOF / 64, N / 64);
    k_gemm_h<<<gA, 256>>>(x, W);
    k_coeff<<<N, 128>>>(a_i, a_j);
    dim3 gD(N / D_BM, HH);
    k_out_tc<<<gD, 256, SM_BYTES>>>(adj, bias, out);
}